// round 5
// baseline (speedup 1.0000x reference)
#include <cuda_runtime.h>
#include <cuda_bf16.h>
#include <cstdint>
#include <cstddef>

// ---------------- problem constants ----------------
#define TOKENS 8192
#define KDIM 4096
#define NDIM 4096

// ---------------- GEMM tiling ----------------
#define BM 128
#define BN 256
#define BK 64
#define NSTAGE 4
#define KITERS (KDIM / BK)              // 64
#define GEMM_THREADS 512                // 16 warps: 4 (M) x 4 (N)

#define A_STAGE_BYTES (BM * BK * 2)     // 16384
#define B_STAGE_BYTES (BN * BK * 2)     // 32768
#define STAGE_BYTES (A_STAGE_BYTES + B_STAGE_BYTES)  // 49152
// smem: [0,1024) u, [1024,2048) bias, [2048, ...) stages
#define SMEM_BYTES (2048 + NSTAGE * STAGE_BYTES)     // 198656

// ---------------- scratch (static device, no allocs) ----------------
__device__ __align__(1024) __nv_bfloat16 g_xb[(size_t)TOKENS * KDIM];  // x bf16 [t][k]
__device__ __align__(1024) __nv_bfloat16 g_wt[(size_t)NDIM * KDIM];    // W^T bf16 [n][k]
__device__ __align__(1024) float g_rowsum[TOKENS];

// ---------------- PTX helpers (compute_100-safe only) ----------------
static __device__ __forceinline__ uint32_t smem_u32(const void* p) {
    uint32_t a;
    asm("{ .reg .u64 t; cvta.to.shared.u64 t, %1; cvt.u32.u64 %0, t; }" : "=r"(a) : "l"(p));
    return a;
}
// swizzle for 128B rows: XOR byte bits [6:4] with (row & 7)
static __device__ __forceinline__ uint32_t swz128(uint32_t o) {
    return o ^ ((o >> 3) & 0x70);
}
static __device__ __forceinline__ void cp_async16(uint32_t sa, size_t ga) {
    asm volatile("cp.async.cg.shared.global [%0], [%1], 16;" :: "r"(sa), "l"(ga) : "memory");
}
static __device__ __forceinline__ void cp_commit() {
    asm volatile("cp.async.commit_group;" ::: "memory");
}
template <int N>
static __device__ __forceinline__ void cp_wait() {
    asm volatile("cp.async.wait_group %0;" :: "n"(N) : "memory");
}
static __device__ __forceinline__ void ldsm_x4(uint32_t& r0, uint32_t& r1, uint32_t& r2,
                                               uint32_t& r3, uint32_t addr) {
    asm volatile("ldmatrix.sync.aligned.m8n8.x4.shared.b16 {%0,%1,%2,%3}, [%4];"
                 : "=r"(r0), "=r"(r1), "=r"(r2), "=r"(r3) : "r"(addr));
}
static __device__ __forceinline__ void mma_16816(float* c, uint32_t a0, uint32_t a1,
                                                 uint32_t a2, uint32_t a3,
                                                 uint32_t b0, uint32_t b1) {
    asm volatile(
        "mma.sync.aligned.m16n8k16.row.col.f32.bf16.bf16.f32 "
        "{%0,%1,%2,%3}, {%4,%5,%6,%7}, {%8,%9}, {%0,%1,%2,%3};"
        : "+f"(c[0]), "+f"(c[1]), "+f"(c[2]), "+f"(c[3])
        : "r"(a0), "r"(a1), "r"(a2), "r"(a3), "r"(b0), "r"(b1));
}

// ---------------- kernel 1: x -> bf16 + exact fp32 rowsum ----------------
__global__ void __launch_bounds__(256) convert_x_kernel(const float* __restrict__ x) {
    const int t = blockIdx.x;
    const int tid = threadIdx.x;
    const float4* xr = reinterpret_cast<const float4*>(x + (size_t)t * KDIM);
    __nv_bfloat162* ob = reinterpret_cast<__nv_bfloat162*>(g_xb + (size_t)t * KDIM);
    float s = 0.f;
#pragma unroll
    for (int j = 0; j < 4; ++j) {
        int i = tid + j * 256;
        float4 v = xr[i];
        s += (v.x + v.y) + (v.z + v.w);
        ob[2 * i]     = __floats2bfloat162_rn(v.x, v.y);
        ob[2 * i + 1] = __floats2bfloat162_rn(v.z, v.w);
    }
#pragma unroll
    for (int off = 16; off; off >>= 1) s += __shfl_xor_sync(0xFFFFFFFFu, s, off);
    __shared__ float red[8];
    if ((tid & 31) == 0) red[tid >> 5] = s;
    __syncthreads();
    if (tid == 0) {
        float tt = 0.f;
#pragma unroll
        for (int i = 0; i < 8; ++i) tt += red[i];
        g_rowsum[t] = tt;
    }
}

// ---------------- kernel 2: dequant + transpose W ----------------
__global__ void __launch_bounds__(256) dequant_w_kernel(const int* __restrict__ Wq,
                                                        const float* __restrict__ scales) {
    __shared__ __nv_bfloat16 tile[32][33];
    const int n0 = blockIdx.x * 32;
    const int k0 = blockIdx.y * 32;
    const int tx = threadIdx.x;       // 0..31
    const int ty = threadIdx.y;       // 0..7
    const float sc = scales[(size_t)(k0 >> 7) * NDIM + n0 + tx];
#pragma unroll
    for (int i = 0; i < 4; ++i) {
        int r = ty + i * 8;
        int q = Wq[(size_t)(k0 + r) * NDIM + n0 + tx];
        tile[r][tx] = __float2bfloat16_rn((float)(q - 8) * sc);
    }
    __syncthreads();
#pragma unroll
    for (int i = 0; i < 4; ++i) {
        int c = ty + i * 8;
        g_wt[(size_t)(n0 + c) * KDIM + k0 + tx] = tile[tx][c];
    }
}

// ---------------- kernel 3: mma.sync bf16 GEMM + fused epilogue ----------------
__global__ void __launch_bounds__(GEMM_THREADS, 1)
gemm_kernel(const float* __restrict__ u, const float* __restrict__ bias,
            float* __restrict__ out) {
    extern __shared__ char smem[];
    float* u_s = reinterpret_cast<float*>(smem);
    float* b_s = reinterpret_cast<float*>(smem + 1024);
    const uint32_t tiles = smem_u32(smem) + 2048;

    const int tid = threadIdx.x;
    const int wid = tid >> 5;
    const int lane = tid & 31;
    const int wm = wid & 3;           // warp row   (4 x 32 = 128)
    const int wn = wid >> 2;          // warp col   (4 x 64 = 256)
    const int n0 = blockIdx.x * BN;
    const int m0 = blockIdx.y * BM;

    // stage u + bias
    if (tid < 256) {
        u_s[tid] = u[n0 + tid];
        b_s[tid] = bias[n0 + tid];
    }

    const size_t ga0 = __cvta_generic_to_global(g_xb) + ((size_t)m0 * KDIM) * 2;
    const size_t gb0 = __cvta_generic_to_global(g_wt) + ((size_t)n0 * KDIM) * 2;

    // producer helper: fill stage s with k-iter `it`
    auto issue = [&](int it, int s) {
        const uint32_t a_s = tiles + s * STAGE_BYTES;
        const uint32_t b_sm = a_s + A_STAGE_BYTES;
        const size_t koff = (size_t)(it * BK) * 2;
        // A: 128 rows x 8 chunks of 16B = 1024 chunks
#pragma unroll
        for (int i = 0; i < 2; ++i) {
            int c = tid + i * 512;
            int row = c >> 3, kc = (c & 7) * 16;
            cp_async16(a_s + swz128((uint32_t)(row * 128 + kc)),
                       ga0 + (size_t)row * (KDIM * 2) + koff + kc);
        }
        // B: 256 rows x 8 chunks = 2048 chunks
#pragma unroll
        for (int i = 0; i < 4; ++i) {
            int c = tid + i * 512;
            int row = c >> 3, kc = (c & 7) * 16;
            cp_async16(b_sm + swz128((uint32_t)(row * 128 + kc)),
                       gb0 + (size_t)row * (KDIM * 2) + koff + kc);
        }
        cp_commit();
    };

    // prologue: stages 0..NSTAGE-2
#pragma unroll
    for (int s = 0; s < NSTAGE - 1; ++s) issue(s, s);

    float acc[2][8][4];
#pragma unroll
    for (int mt = 0; mt < 2; ++mt)
#pragma unroll
        for (int nt = 0; nt < 8; ++nt)
#pragma unroll
            for (int j = 0; j < 4; ++j) acc[mt][nt][j] = 0.f;

    // ldmatrix per-lane row/col selectors (same for A and B: 128B rows)
    const int lrow = lane & 15;               // row within 16-row block
    const int lkb = (lane >> 4) * 16;         // +8 cols -> +16 bytes

    for (int it = 0; it < KITERS; ++it) {
        cp_wait<NSTAGE - 2>();
        __syncthreads();
        // This barrier proves all threads finished iteration it-1, whose reads
        // targeted stage (it-1)%NSTAGE == (it+NSTAGE-1)%NSTAGE — exactly the
        // stage refilled below. So a single barrier per iteration suffices and
        // the cp.async issue overlaps this iteration's compute.
        if (it + NSTAGE - 1 < KITERS) issue(it + NSTAGE - 1, (it + NSTAGE - 1) % NSTAGE);

        const int s = it % NSTAGE;
        const uint32_t a_s = tiles + s * STAGE_BYTES;
        const uint32_t b_sm = a_s + A_STAGE_BYTES;

#pragma unroll
        for (int ks = 0; ks < BK / 16; ++ks) {
            const uint32_t kbyte = ks * 32 + lkb;
            // A frags: 2 m-tiles of 16
            uint32_t a[2][4];
#pragma unroll
            for (int mt = 0; mt < 2; ++mt) {
                const int row = wm * 32 + mt * 16 + lrow;
                ldsm_x4(a[mt][0], a[mt][1], a[mt][2], a[mt][3],
                        a_s + swz128((uint32_t)(row * 128) + kbyte));
            }
            // B frags: 4 n-pairs of 16
            uint32_t b[4][4];
#pragma unroll
            for (int p = 0; p < 4; ++p) {
                const int row = wn * 64 + p * 16 + lrow;
                ldsm_x4(b[p][0], b[p][1], b[p][2], b[p][3],
                        b_sm + swz128((uint32_t)(row * 128) + kbyte));
            }
#pragma unroll
            for (int mt = 0; mt < 2; ++mt)
#pragma unroll
                for (int nt = 0; nt < 8; ++nt) {
                    const int p = nt >> 1, h = nt & 1;
                    mma_16816(acc[mt][nt], a[mt][0], a[mt][1], a[mt][2], a[mt][3],
                              b[p][h], b[p][2 + h]);
                }
        }
    }

    // -------- epilogue: out = acc + rowsum*u + bias --------
#pragma unroll
    for (int mt = 0; mt < 2; ++mt) {
        const int r0 = m0 + wm * 32 + mt * 16 + (lane >> 2);
        const float rs0 = g_rowsum[r0];
        const float rs1 = g_rowsum[r0 + 8];
        float* o0 = out + (size_t)r0 * NDIM + n0;
        float* o1 = out + (size_t)(r0 + 8) * NDIM + n0;
#pragma unroll
        for (int nt = 0; nt < 8; ++nt) {
            const int c = wn * 64 + nt * 8 + (lane & 3) * 2;
            const float u0 = u_s[c], u1 = u_s[c + 1];
            const float bb0 = b_s[c], bb1 = b_s[c + 1];
            float2 v0, v1;
            v0.x = acc[mt][nt][0] + rs0 * u0 + bb0;
            v0.y = acc[mt][nt][1] + rs0 * u1 + bb1;
            v1.x = acc[mt][nt][2] + rs1 * u0 + bb0;
            v1.y = acc[mt][nt][3] + rs1 * u1 + bb1;
            *reinterpret_cast<float2*>(o0 + c) = v0;
            *reinterpret_cast<float2*>(o1 + c) = v1;
        }
    }
}

// ---------------- launch ----------------
extern "C" void kernel_launch(void* const* d_in, const int* in_sizes, int n_in,
                              void* d_out, int out_size) {
    const float* x      = (const float*)d_in[0];   // [4*2048*4096]
    const int*   Wq     = (const int*)d_in[1];     // [4096*4096]
    const float* scales = (const float*)d_in[2];   // [32*4096]
    const float* u      = (const float*)d_in[3];   // [4096]
    const float* bias   = (const float*)d_in[4];   // [4096]
    float* out = (float*)d_out;

    cudaFuncSetAttribute(gemm_kernel, cudaFuncAttributeMaxDynamicSharedMemorySize, SMEM_BYTES);

    convert_x_kernel<<<TOKENS, 256>>>(x);
    dequant_w_kernel<<<dim3(NDIM / 32, KDIM / 32), dim3(32, 8)>>>(Wq, scales);
    gemm_kernel<<<dim3(NDIM / BN, TOKENS / BM), GEMM_THREADS, SMEM_BYTES>>>(u, bias, out);
}

// round 6
// speedup vs baseline: 1.3477x; 1.3477x over previous
#include <cuda_runtime.h>
#include <cuda_bf16.h>
#include <cstdint>
#include <cstddef>

// ---------------- problem constants ----------------
#define TOKENS 8192
#define KDIM 4096
#define NDIM 4096
#define NGROUP 32                       // KDIM / 128

// ---------------- GEMM tiling ----------------
#define BM 128
#define BN 128
#define BK 128                          // one quant group per k-iter
#define NSTAGE 4
#define KITERS (KDIM / BK)              // 32
#define GEMM_THREADS 512                // 16 warps: 4 (M) x 4 (N), 32x32 each

#define A_STAGE_BYTES (BM * BK)         // 16384 (int8)
#define B_STAGE_BYTES (BN * BK)         // 16384 (int8)
#define STAGE_BYTES (A_STAGE_BYTES + B_STAGE_BYTES)   // 32768
// smem: [0,512) u, [512,1024) bias, [1024,17408) scales[32][128], stages after
#define SC_OFF 1024
#define TILE_OFF 17408
#define SMEM_BYTES (TILE_OFF + NSTAGE * STAGE_BYTES)  // 148480

// ---------------- scratch (static device, no allocs) ----------------
__device__ __align__(1024) int8_t g_xq[(size_t)TOKENS * KDIM];   // quantized x [t][k]
__device__ __align__(1024) int8_t g_wti[(size_t)NDIM * KDIM];    // (q-8) transposed [n][k]
__device__ __align__(1024) float g_rowsum[TOKENS];
__device__ __align__(1024) float g_xscale[TOKENS];

// ---------------- PTX helpers (compute_100-safe only) ----------------
static __device__ __forceinline__ uint32_t smem_u32(const void* p) {
    uint32_t a;
    asm("{ .reg .u64 t; cvta.to.shared.u64 t, %1; cvt.u32.u64 %0, t; }" : "=r"(a) : "l"(p));
    return a;
}
static __device__ __forceinline__ uint32_t swz128(uint32_t o) {
    return o ^ ((o >> 3) & 0x70);
}
static __device__ __forceinline__ void cp_async16(uint32_t sa, size_t ga) {
    asm volatile("cp.async.cg.shared.global [%0], [%1], 16;" :: "r"(sa), "l"(ga) : "memory");
}
static __device__ __forceinline__ void cp_commit() {
    asm volatile("cp.async.commit_group;" ::: "memory");
}
template <int N>
static __device__ __forceinline__ void cp_wait() {
    asm volatile("cp.async.wait_group %0;" :: "n"(N) : "memory");
}
static __device__ __forceinline__ void ldsm_x4(uint32_t& r0, uint32_t& r1, uint32_t& r2,
                                               uint32_t& r3, uint32_t addr) {
    asm volatile("ldmatrix.sync.aligned.m8n8.x4.shared.b16 {%0,%1,%2,%3}, [%4];"
                 : "=r"(r0), "=r"(r1), "=r"(r2), "=r"(r3) : "r"(addr));
}
// int8 MMA: D(s32) = A(s8,row) x B(s8,col) + C(s32)
static __device__ __forceinline__ void mma_s8(int* c, uint32_t a0, uint32_t a1,
                                              uint32_t a2, uint32_t a3,
                                              uint32_t b0, uint32_t b1) {
    asm volatile(
        "mma.sync.aligned.m16n8k32.row.col.s32.s8.s8.s32 "
        "{%0,%1,%2,%3}, {%4,%5,%6,%7}, {%8,%9}, {%0,%1,%2,%3};"
        : "+r"(c[0]), "+r"(c[1]), "+r"(c[2]), "+r"(c[3])
        : "r"(a0), "r"(a1), "r"(a2), "r"(a3), "r"(b0), "r"(b1));
}
static __device__ __forceinline__ uint32_t pack4(float a, float b, float c, float d, float inv) {
    int qa = __float2int_rn(a * inv), qb = __float2int_rn(b * inv);
    int qc = __float2int_rn(c * inv), qd = __float2int_rn(d * inv);
    return (uint32_t)(qa & 255) | ((uint32_t)(qb & 255) << 8) |
           ((uint32_t)(qc & 255) << 16) | ((uint32_t)(qd & 255) << 24);
}

// ---------------- kernel 1: x -> int8 (per-token scale) + exact fp32 rowsum ----------------
__global__ void __launch_bounds__(256) convert_x_kernel(const float* __restrict__ x) {
    const int t = blockIdx.x;
    const int tid = threadIdx.x;
    const float4* xr = reinterpret_cast<const float4*>(x + (size_t)t * KDIM);
    float4 v[4];
    float s = 0.f, mx = 0.f;
#pragma unroll
    for (int j = 0; j < 4; ++j) {
        v[j] = xr[tid * 4 + j];                    // thread owns floats [tid*16, tid*16+16)
        s += (v[j].x + v[j].y) + (v[j].z + v[j].w);
        mx = fmaxf(mx, fmaxf(fmaxf(fabsf(v[j].x), fabsf(v[j].y)),
                             fmaxf(fabsf(v[j].z), fabsf(v[j].w))));
    }
#pragma unroll
    for (int off = 16; off; off >>= 1) {
        s += __shfl_xor_sync(0xFFFFFFFFu, s, off);
        mx = fmaxf(mx, __shfl_xor_sync(0xFFFFFFFFu, mx, off));
    }
    __shared__ float rsum[8], rmax[8], bc[2];
    if ((tid & 31) == 0) { rsum[tid >> 5] = s; rmax[tid >> 5] = mx; }
    __syncthreads();
    if (tid == 0) {
        float ts = 0.f, tm = 0.f;
#pragma unroll
        for (int i = 0; i < 8; ++i) { ts += rsum[i]; tm = fmaxf(tm, rmax[i]); }
        g_rowsum[t] = ts;
        g_xscale[t] = tm * (1.f / 127.f);
        bc[0] = (tm > 0.f) ? (127.f / tm) : 0.f;
    }
    __syncthreads();
    const float inv = bc[0];
    uint4 o;
    o.x = pack4(v[0].x, v[0].y, v[0].z, v[0].w, inv);
    o.y = pack4(v[1].x, v[1].y, v[1].z, v[1].w, inv);
    o.z = pack4(v[2].x, v[2].y, v[2].z, v[2].w, inv);
    o.w = pack4(v[3].x, v[3].y, v[3].z, v[3].w, inv);
    *reinterpret_cast<uint4*>(g_xq + (size_t)t * KDIM + tid * 16) = o;
}

// ---------------- kernel 2: Wq int32 [k][n] -> int8 (q-8) transposed [n][k] ----------------
__global__ void __launch_bounds__(256) transpose_w_kernel(const int* __restrict__ Wq) {
    __shared__ int8_t tile[32][144];      // 32 n-rows x 128 k + pad (16B-aligned rows)
    const int n0 = blockIdx.x * 32;
    const int k0 = blockIdx.y * 128;
    const int tx = threadIdx.x & 31;      // n within tile
    const int ty = threadIdx.x >> 5;      // 0..7
#pragma unroll
    for (int kk = 0; kk < 16; ++kk) {
        const int kr = ty * 16 + kk;
        const int q = Wq[(size_t)(k0 + kr) * NDIM + n0 + tx];
        tile[tx][kr] = (int8_t)(q - 8);
    }
    __syncthreads();
    const int n = threadIdx.x >> 3;
    const int off = (threadIdx.x & 7) * 16;
    uint4 val = *reinterpret_cast<const uint4*>(&tile[n][off]);
    *reinterpret_cast<uint4*>(g_wti + (size_t)(n0 + n) * KDIM + k0 + off) = val;
}

// ---------------- kernel 3: int8 mma GEMM, per-group dequant, fused epilogue ----------------
__global__ void __launch_bounds__(GEMM_THREADS, 1)
gemm_kernel(const float* __restrict__ scales, const float* __restrict__ u,
            const float* __restrict__ bias, float* __restrict__ out) {
    extern __shared__ char smem[];
    float* u_s  = reinterpret_cast<float*>(smem);
    float* b_s  = reinterpret_cast<float*>(smem + 512);
    float* sc_s = reinterpret_cast<float*>(smem + SC_OFF);   // [32 groups][128 n]
    const uint32_t tiles = smem_u32(smem) + TILE_OFF;

    const int tid = threadIdx.x;
    const int wid = tid >> 5;
    const int lane = tid & 31;
    const int wm = wid & 3;               // 4 x 32 = 128 M
    const int wn = wid >> 2;              // 4 x 32 = 128 N
    const int n0 = blockIdx.x * BN;
    const int m0 = blockIdx.y * BM;

    if (tid < 128) { u_s[tid] = u[n0 + tid]; b_s[tid] = bias[n0 + tid]; }
#pragma unroll
    for (int i = tid; i < NGROUP * 128; i += GEMM_THREADS)
        sc_s[i] = scales[(size_t)(i >> 7) * NDIM + n0 + (i & 127)];

    const size_t ga0 = __cvta_generic_to_global(g_xq) + (size_t)m0 * KDIM;
    const size_t gb0 = __cvta_generic_to_global(g_wti) + (size_t)n0 * KDIM;

    auto issue = [&](int it, int s) {
        const uint32_t a_s = tiles + s * STAGE_BYTES;
        const uint32_t b_sm = a_s + A_STAGE_BYTES;
        const size_t koff = (size_t)it * BK;
        // A: 128 rows x 8 chunks of 16B = 1024 chunks; B same
#pragma unroll
        for (int i = 0; i < 2; ++i) {
            int c = tid + i * 512;
            int row = c >> 3, kc = (c & 7) * 16;
            cp_async16(a_s + swz128((uint32_t)(row * 128 + kc)),
                       ga0 + (size_t)row * KDIM + koff + kc);
        }
#pragma unroll
        for (int i = 0; i < 2; ++i) {
            int c = tid + i * 512;
            int row = c >> 3, kc = (c & 7) * 16;
            cp_async16(b_sm + swz128((uint32_t)(row * 128 + kc)),
                       gb0 + (size_t)row * KDIM + koff + kc);
        }
        cp_commit();
    };

#pragma unroll
    for (int s = 0; s < NSTAGE - 1; ++s) issue(s, s);

    float acc_f[2][4][4];
#pragma unroll
    for (int mt = 0; mt < 2; ++mt)
#pragma unroll
        for (int nt = 0; nt < 4; ++nt)
#pragma unroll
            for (int j = 0; j < 4; ++j) acc_f[mt][nt][j] = 0.f;

    const int lrow = lane & 15;
    const int lkb = (lane >> 4) * 16;
    const int cb = wn * 32 + (lane & 3) * 2;   // base output column for this lane

    __syncthreads();   // sc_s / u_s ready before anyone reads them later

    for (int it = 0; it < KITERS; ++it) {
        cp_wait<NSTAGE - 2>();
        __syncthreads();
        if (it + NSTAGE - 1 < KITERS) issue(it + NSTAGE - 1, (it + NSTAGE - 1) % NSTAGE);

        const int s = it % NSTAGE;
        const uint32_t a_s = tiles + s * STAGE_BYTES;
        const uint32_t b_sm = a_s + A_STAGE_BYTES;

        int acc_i[2][4][4];
#pragma unroll
        for (int mt = 0; mt < 2; ++mt)
#pragma unroll
            for (int nt = 0; nt < 4; ++nt)
#pragma unroll
                for (int j = 0; j < 4; ++j) acc_i[mt][nt][j] = 0;

#pragma unroll
        for (int ks = 0; ks < 4; ++ks) {   // 4 x k32 = one 128-wide group
            const uint32_t kbyte = ks * 32 + lkb;
            uint32_t a[2][4];
#pragma unroll
            for (int mt = 0; mt < 2; ++mt) {
                const int row = wm * 32 + mt * 16 + lrow;
                ldsm_x4(a[mt][0], a[mt][1], a[mt][2], a[mt][3],
                        a_s + swz128((uint32_t)(row * 128) + kbyte));
            }
            uint32_t b[2][4];
#pragma unroll
            for (int p = 0; p < 2; ++p) {
                const int row = wn * 32 + p * 16 + lrow;
                ldsm_x4(b[p][0], b[p][1], b[p][2], b[p][3],
                        b_sm + swz128((uint32_t)(row * 128) + kbyte));
            }
#pragma unroll
            for (int mt = 0; mt < 2; ++mt)
#pragma unroll
                for (int nt = 0; nt < 4; ++nt) {
                    const int p = nt >> 1, h = nt & 1;
                    mma_s8(acc_i[mt][nt], a[mt][0], a[mt][1], a[mt][2], a[mt][3],
                           b[p][h], b[p][2 + h]);
                }
        }
        // per-group dequant into fp32 accumulators
        const float* scg = sc_s + it * 128;
#pragma unroll
        for (int nt = 0; nt < 4; ++nt) {
            const int c0 = cb + nt * 8;
            const float s0 = scg[c0], s1 = scg[c0 + 1];
#pragma unroll
            for (int mt = 0; mt < 2; ++mt) {
                acc_f[mt][nt][0] += s0 * (float)acc_i[mt][nt][0];
                acc_f[mt][nt][1] += s1 * (float)acc_i[mt][nt][1];
                acc_f[mt][nt][2] += s0 * (float)acc_i[mt][nt][2];
                acc_f[mt][nt][3] += s1 * (float)acc_i[mt][nt][3];
            }
        }
    }

    // -------- epilogue: out = sx*acc + rowsum*u + bias --------
#pragma unroll
    for (int mt = 0; mt < 2; ++mt) {
        const int r0 = m0 + wm * 32 + mt * 16 + (lane >> 2);
        const float sx0 = g_xscale[r0], sx1 = g_xscale[r0 + 8];
        const float rs0 = g_rowsum[r0], rs1 = g_rowsum[r0 + 8];
        float* o0 = out + (size_t)r0 * NDIM + n0;
        float* o1 = out + (size_t)(r0 + 8) * NDIM + n0;
#pragma unroll
        for (int nt = 0; nt < 4; ++nt) {
            const int c = cb + nt * 8;
            const float u0 = u_s[c], u1 = u_s[c + 1];
            const float bb0 = b_s[c], bb1 = b_s[c + 1];
            float2 v0, v1;
            v0.x = sx0 * acc_f[mt][nt][0] + rs0 * u0 + bb0;
            v0.y = sx0 * acc_f[mt][nt][1] + rs0 * u1 + bb1;
            v1.x = sx1 * acc_f[mt][nt][2] + rs1 * u0 + bb0;
            v1.y = sx1 * acc_f[mt][nt][3] + rs1 * u1 + bb1;
            *reinterpret_cast<float2*>(o0 + c) = v0;
            *reinterpret_cast<float2*>(o1 + c) = v1;
        }
    }
}

// ---------------- launch ----------------
extern "C" void kernel_launch(void* const* d_in, const int* in_sizes, int n_in,
                              void* d_out, int out_size) {
    const float* x      = (const float*)d_in[0];   // [4*2048*4096]
    const int*   Wq     = (const int*)d_in[1];     // [4096*4096]
    const float* scales = (const float*)d_in[2];   // [32*4096]
    const float* u      = (const float*)d_in[3];   // [4096]
    const float* bias   = (const float*)d_in[4];   // [4096]
    float* out = (float*)d_out;

    cudaFuncSetAttribute(gemm_kernel, cudaFuncAttributeMaxDynamicSharedMemorySize, SMEM_BYTES);

    convert_x_kernel<<<TOKENS, 256>>>(x);
    transpose_w_kernel<<<dim3(NDIM / 32, KDIM / 128), 256>>>(Wq);
    gemm_kernel<<<dim3(NDIM / BN, TOKENS / BM), GEMM_THREADS, SMEM_BYTES>>>(scales, u, bias, out);
}

// round 8
// speedup vs baseline: 1.3977x; 1.0371x over previous
#include <cuda_runtime.h>
#include <cuda_bf16.h>
#include <cstdint>
#include <cstddef>

// ---------------- problem constants ----------------
#define TOKENS 8192
#define KDIM 4096
#define NDIM 4096
#define NGROUP 32                       // KDIM / 128

// ---------------- GEMM tiling ----------------
#define BM 128
#define BN 128
#define BK 128                          // one quant group per k-iter
#define NSTAGE 4
#define KITERS (KDIM / BK)              // 32
#define GEMM_THREADS 256                // 8 warps: 4 (M) x 2 (N), 32x64 each

#define A_STAGE_BYTES (BM * BK)         // 16384 (int8)
#define B_STAGE_BYTES (BN * BK)         // 16384 (int8)
#define STAGE_BYTES (A_STAGE_BYTES + B_STAGE_BYTES)   // 32768
// smem: [0,512) u, [512,1024) bias, [1024,17408) scales[32][128], stages after
#define SC_OFF 1024
#define TILE_OFF 17408
#define SMEM_BYTES (TILE_OFF + NSTAGE * STAGE_BYTES)  // 148480

// ---------------- scratch (static device, no allocs) ----------------
__device__ __align__(1024) int8_t g_xq[(size_t)TOKENS * KDIM];   // quantized x [t][k]
__device__ __align__(1024) int8_t g_wti[(size_t)NDIM * KDIM];    // (q-8) transposed [n][k]
__device__ __align__(1024) float g_rowsum[TOKENS];
__device__ __align__(1024) float g_xscale[TOKENS];

// ---------------- PTX helpers (compute_100-safe only) ----------------
static __device__ __forceinline__ uint32_t smem_u32(const void* p) {
    uint32_t a;
    asm("{ .reg .u64 t; cvta.to.shared.u64 t, %1; cvt.u32.u64 %0, t; }" : "=r"(a) : "l"(p));
    return a;
}
static __device__ __forceinline__ uint32_t swz128(uint32_t o) {
    return o ^ ((o >> 3) & 0x70);
}
static __device__ __forceinline__ void cp_async16(uint32_t sa, size_t ga) {
    asm volatile("cp.async.cg.shared.global [%0], [%1], 16;" :: "r"(sa), "l"(ga) : "memory");
}
static __device__ __forceinline__ void cp_commit() {
    asm volatile("cp.async.commit_group;" ::: "memory");
}
template <int N>
static __device__ __forceinline__ void cp_wait() {
    asm volatile("cp.async.wait_group %0;" :: "n"(N) : "memory");
}
static __device__ __forceinline__ void ldsm_x4(uint32_t& r0, uint32_t& r1, uint32_t& r2,
                                               uint32_t& r3, uint32_t addr) {
    asm volatile("ldmatrix.sync.aligned.m8n8.x4.shared.b16 {%0,%1,%2,%3}, [%4];"
                 : "=r"(r0), "=r"(r1), "=r"(r2), "=r"(r3) : "r"(addr));
}
// int8 MMA: D(s32) = A(s8,row) x B(s8,col) + C(s32)
static __device__ __forceinline__ void mma_s8(int* c, uint32_t a0, uint32_t a1,
                                              uint32_t a2, uint32_t a3,
                                              uint32_t b0, uint32_t b1) {
    asm volatile(
        "mma.sync.aligned.m16n8k32.row.col.s32.s8.s8.s32 "
        "{%0,%1,%2,%3}, {%4,%5,%6,%7}, {%8,%9}, {%0,%1,%2,%3};"
        : "+r"(c[0]), "+r"(c[1]), "+r"(c[2]), "+r"(c[3])
        : "r"(a0), "r"(a1), "r"(a2), "r"(a3), "r"(b0), "r"(b1));
}
static __device__ __forceinline__ uint32_t pack4(float a, float b, float c, float d, float inv) {
    int qa = __float2int_rn(a * inv), qb = __float2int_rn(b * inv);
    int qc = __float2int_rn(c * inv), qd = __float2int_rn(d * inv);
    return (uint32_t)(qa & 255) | ((uint32_t)(qb & 255) << 8) |
           ((uint32_t)(qc & 255) << 16) | ((uint32_t)(qd & 255) << 24);
}

// ---------------- kernel 1 (fused prep): x->int8 + rowsum  |  Wq->int8 transposed ----
// blocks [0, TOKENS): convert token;  blocks [TOKENS, TOKENS+4096): transpose tile.
__global__ void __launch_bounds__(256) prep_kernel(const float* __restrict__ x,
                                                   const int* __restrict__ Wq) {
    // Single aligned shared frame for BOTH branches. The uint4 reads from
    // `tile` require 16B base alignment — in the round-7 version the float
    // scalars of the other branch pushed `tile` to offset 68 and every
    // ld.shared.v4 trapped with "misaligned address".
    __shared__ __align__(16) int8_t tile[32][144];
    float* rsum = reinterpret_cast<float*>(&tile[0][0]);        // reuse, branch-exclusive
    float* rmax = reinterpret_cast<float*>(&tile[0][64]);
    float* bc   = reinterpret_cast<float*>(&tile[1][0]);

    if (blockIdx.x < TOKENS) {
        const int t = blockIdx.x;
        const int tid = threadIdx.x;
        const float4* xr = reinterpret_cast<const float4*>(x + (size_t)t * KDIM);
        float4 v[4];
        float s = 0.f, mx = 0.f;
#pragma unroll
        for (int j = 0; j < 4; ++j) {
            v[j] = xr[tid * 4 + j];
            s += (v[j].x + v[j].y) + (v[j].z + v[j].w);
            mx = fmaxf(mx, fmaxf(fmaxf(fabsf(v[j].x), fabsf(v[j].y)),
                                 fmaxf(fabsf(v[j].z), fabsf(v[j].w))));
        }
#pragma unroll
        for (int off = 16; off; off >>= 1) {
            s += __shfl_xor_sync(0xFFFFFFFFu, s, off);
            mx = fmaxf(mx, __shfl_xor_sync(0xFFFFFFFFu, mx, off));
        }
        if ((tid & 31) == 0) { rsum[tid >> 5] = s; rmax[tid >> 5] = mx; }
        __syncthreads();
        if (tid == 0) {
            float ts = 0.f, tm = 0.f;
#pragma unroll
            for (int i = 0; i < 8; ++i) { ts += rsum[i]; tm = fmaxf(tm, rmax[i]); }
            g_rowsum[t] = ts;
            g_xscale[t] = tm * (1.f / 127.f);
            bc[0] = (tm > 0.f) ? (127.f / tm) : 0.f;
        }
        __syncthreads();
        const float inv = bc[0];
        uint4 o;
        o.x = pack4(v[0].x, v[0].y, v[0].z, v[0].w, inv);
        o.y = pack4(v[1].x, v[1].y, v[1].z, v[1].w, inv);
        o.z = pack4(v[2].x, v[2].y, v[2].z, v[2].w, inv);
        o.w = pack4(v[3].x, v[3].y, v[3].z, v[3].w, inv);
        *reinterpret_cast<uint4*>(g_xq + (size_t)t * KDIM + tid * 16) = o;
    } else {
        const int idx = blockIdx.x - TOKENS;
        const int n0 = (idx & 127) * 32;
        const int k0 = (idx >> 7) * 128;
        const int tx = threadIdx.x & 31;      // n within tile
        const int ty = threadIdx.x >> 5;      // 0..7
#pragma unroll
        for (int kk = 0; kk < 16; ++kk) {
            const int kr = ty * 16 + kk;
            const int q = Wq[(size_t)(k0 + kr) * NDIM + n0 + tx];
            tile[tx][kr] = (int8_t)(q - 8);
        }
        __syncthreads();
        const int n = threadIdx.x >> 3;
        const int off = (threadIdx.x & 7) * 16;
        uint4 val = *reinterpret_cast<const uint4*>(&tile[n][off]);
        *reinterpret_cast<uint4*>(g_wti + (size_t)(n0 + n) * KDIM + k0 + off) = val;
    }
}

// ---------------- kernel 2: int8 mma GEMM, per-group dequant, fused epilogue ----------------
__global__ void __launch_bounds__(GEMM_THREADS, 1)
gemm_kernel(const float* __restrict__ scales, const float* __restrict__ u,
            const float* __restrict__ bias, float* __restrict__ out) {
    extern __shared__ char smem[];
    float* u_s  = reinterpret_cast<float*>(smem);
    float* b_s  = reinterpret_cast<float*>(smem + 512);
    float* sc_s = reinterpret_cast<float*>(smem + SC_OFF);   // [32 groups][128 n]
    const uint32_t tiles = smem_u32(smem) + TILE_OFF;

    const int tid = threadIdx.x;
    const int wid = tid >> 5;
    const int lane = tid & 31;
    const int wm = wid & 3;               // 4 x 32 = 128 M
    const int wn = wid >> 2;              // 2 x 64 = 128 N
    const int n0 = blockIdx.x * BN;
    const int m0 = blockIdx.y * BM;

    if (tid < 128) { u_s[tid] = u[n0 + tid]; b_s[tid] = bias[n0 + tid]; }
#pragma unroll
    for (int i = tid; i < NGROUP * 128; i += GEMM_THREADS)
        sc_s[i] = scales[(size_t)(i >> 7) * NDIM + n0 + (i & 127)];

    const size_t ga0 = __cvta_generic_to_global(g_xq) + (size_t)m0 * KDIM;
    const size_t gb0 = __cvta_generic_to_global(g_wti) + (size_t)n0 * KDIM;

    auto issue = [&](int it, int s) {
        const uint32_t a_s = tiles + s * STAGE_BYTES;
        const uint32_t b_sm = a_s + A_STAGE_BYTES;
        const size_t koff = (size_t)it * BK;
        // A: 1024 16B chunks; B: 1024 chunks; 256 threads -> 4+4 each
#pragma unroll
        for (int i = 0; i < 4; ++i) {
            int c = tid + i * 256;
            int row = c >> 3, kc = (c & 7) * 16;
            cp_async16(a_s + swz128((uint32_t)(row * 128 + kc)),
                       ga0 + (size_t)row * KDIM + koff + kc);
        }
#pragma unroll
        for (int i = 0; i < 4; ++i) {
            int c = tid + i * 256;
            int row = c >> 3, kc = (c & 7) * 16;
            cp_async16(b_sm + swz128((uint32_t)(row * 128 + kc)),
                       gb0 + (size_t)row * KDIM + koff + kc);
        }
        cp_commit();
    };

#pragma unroll
    for (int s = 0; s < NSTAGE - 1; ++s) issue(s, s);

    float acc_f[2][8][4];
#pragma unroll
    for (int mt = 0; mt < 2; ++mt)
#pragma unroll
        for (int nt = 0; nt < 8; ++nt)
#pragma unroll
            for (int j = 0; j < 4; ++j) acc_f[mt][nt][j] = 0.f;

    const int lrow = lane & 15;
    const int lkb = (lane >> 4) * 16;
    const int cb = wn * 64 + (lane & 3) * 2;   // base output column for this lane

    __syncthreads();   // sc_s / u_s ready

    for (int it = 0; it < KITERS; ++it) {
        cp_wait<NSTAGE - 2>();
        __syncthreads();
        if (it + NSTAGE - 1 < KITERS) issue(it + NSTAGE - 1, (it + NSTAGE - 1) % NSTAGE);

        const int s = it % NSTAGE;
        const uint32_t a_s = tiles + s * STAGE_BYTES;
        const uint32_t b_sm = a_s + A_STAGE_BYTES;

        int acc_i[2][8][4];
#pragma unroll
        for (int mt = 0; mt < 2; ++mt)
#pragma unroll
            for (int nt = 0; nt < 8; ++nt)
#pragma unroll
                for (int j = 0; j < 4; ++j) acc_i[mt][nt][j] = 0;

#pragma unroll
        for (int ks = 0; ks < 4; ++ks) {   // 4 x k32 = one 128-wide group
            const uint32_t kbyte = ks * 32 + lkb;
            uint32_t a[2][4];
#pragma unroll
            for (int mt = 0; mt < 2; ++mt) {
                const int row = wm * 32 + mt * 16 + lrow;
                ldsm_x4(a[mt][0], a[mt][1], a[mt][2], a[mt][3],
                        a_s + swz128((uint32_t)(row * 128) + kbyte));
            }
            uint32_t b[4][4];
#pragma unroll
            for (int p = 0; p < 4; ++p) {
                const int row = wn * 64 + p * 16 + lrow;
                ldsm_x4(b[p][0], b[p][1], b[p][2], b[p][3],
                        b_sm + swz128((uint32_t)(row * 128) + kbyte));
            }
#pragma unroll
            for (int mt = 0; mt < 2; ++mt)
#pragma unroll
                for (int nt = 0; nt < 8; ++nt) {
                    const int p = nt >> 1, h = nt & 1;
                    mma_s8(acc_i[mt][nt], a[mt][0], a[mt][1], a[mt][2], a[mt][3],
                           b[p][h], b[p][2 + h]);
                }
        }
        // per-group dequant into fp32 accumulators
        const float* scg = sc_s + it * 128;
#pragma unroll
        for (int nt = 0; nt < 8; ++nt) {
            const int c0 = cb + nt * 8;
            const float s0 = scg[c0], s1 = scg[c0 + 1];
#pragma unroll
            for (int mt = 0; mt < 2; ++mt) {
                acc_f[mt][nt][0] += s0 * (float)acc_i[mt][nt][0];
                acc_f[mt][nt][1] += s1 * (float)acc_i[mt][nt][1];
                acc_f[mt][nt][2] += s0 * (float)acc_i[mt][nt][2];
                acc_f[mt][nt][3] += s1 * (float)acc_i[mt][nt][3];
            }
        }
    }

    // -------- epilogue: out = sx*acc + rowsum*u + bias --------
#pragma unroll
    for (int mt = 0; mt < 2; ++mt) {
        const int r0 = m0 + wm * 32 + mt * 16 + (lane >> 2);
        const float sx0 = g_xscale[r0], sx1 = g_xscale[r0 + 8];
        const float rs0 = g_rowsum[r0], rs1 = g_rowsum[r0 + 8];
        float* o0 = out + (size_t)r0 * NDIM + n0;
        float* o1 = out + (size_t)(r0 + 8) * NDIM + n0;
#pragma unroll
        for (int nt = 0; nt < 8; ++nt) {
            const int c = cb + nt * 8;
            const float u0 = u_s[c], u1 = u_s[c + 1];
            const float bb0 = b_s[c], bb1 = b_s[c + 1];
            float2 v0, v1;
            v0.x = sx0 * acc_f[mt][nt][0] + rs0 * u0 + bb0;
            v0.y = sx0 * acc_f[mt][nt][1] + rs0 * u1 + bb1;
            v1.x = sx1 * acc_f[mt][nt][2] + rs1 * u0 + bb0;
            v1.y = sx1 * acc_f[mt][nt][3] + rs1 * u1 + bb1;
            *reinterpret_cast<float2*>(o0 + c) = v0;
            *reinterpret_cast<float2*>(o1 + c) = v1;
        }
    }
}

// ---------------- launch ----------------
extern "C" void kernel_launch(void* const* d_in, const int* in_sizes, int n_in,
                              void* d_out, int out_size) {
    const float* x      = (const float*)d_in[0];   // [4*2048*4096]
    const int*   Wq     = (const int*)d_in[1];     // [4096*4096]
    const float* scales = (const float*)d_in[2];   // [32*4096]
    const float* u      = (const float*)d_in[3];   // [4096]
    const float* bias   = (const float*)d_in[4];   // [4096]
    float* out = (float*)d_out;

    cudaFuncSetAttribute(gemm_kernel, cudaFuncAttributeMaxDynamicSharedMemorySize, SMEM_BYTES);

    prep_kernel<<<TOKENS + 4096, 256>>>(x, Wq);
    gemm_kernel<<<dim3(NDIM / BN, TOKENS / BM), GEMM_THREADS, SMEM_BYTES>>>(scales, u, bias, out);
}

// round 9
// speedup vs baseline: 1.4828x; 1.0608x over previous
#include <cuda_runtime.h>
#include <cuda_bf16.h>
#include <cstdint>
#include <cstddef>

// ---------------- problem constants ----------------
#define TOKENS 8192
#define KDIM 4096
#define NDIM 4096
#define NGROUP 32                       // KDIM / 128

// ---------------- GEMM tiling ----------------
#define BM 128
#define BN 64
#define BK 128                          // one quant group per k-iter
#define NSTAGE 4
#define KITERS (KDIM / BK)              // 32
#define GEMM_THREADS 256                // 8 warps: 4 (M) x 2 (N), 32x32 each

#define A_STAGE_BYTES (BM * BK)         // 16384 (int8)
#define B_STAGE_BYTES (BN * BK)         // 8192 (int8)
#define STAGE_BYTES (A_STAGE_BYTES + B_STAGE_BYTES)   // 24576
// smem: [0,256) u, [256,512) bias, [512,8704) scales[32][64], tiles @9216
#define SC_OFF 512
#define TILE_OFF 9216
#define SMEM_BYTES (TILE_OFF + NSTAGE * STAGE_BYTES)  // 107520  (x2 CTAs = 210KB/SM)

// ---------------- scratch (static device, no allocs) ----------------
__device__ __align__(1024) int8_t g_xq[(size_t)TOKENS * KDIM];   // quantized x [t][k]
__device__ __align__(1024) int8_t g_wti[(size_t)NDIM * KDIM];    // (q-8) transposed [n][k]
__device__ __align__(1024) float g_rowsum[TOKENS];
__device__ __align__(1024) float g_xscale[TOKENS];

// ---------------- PTX helpers (compute_100-safe only) ----------------
static __device__ __forceinline__ uint32_t smem_u32(const void* p) {
    uint32_t a;
    asm("{ .reg .u64 t; cvta.to.shared.u64 t, %1; cvt.u32.u64 %0, t; }" : "=r"(a) : "l"(p));
    return a;
}
static __device__ __forceinline__ uint32_t swz128(uint32_t o) {
    return o ^ ((o >> 3) & 0x70);
}
static __device__ __forceinline__ void cp_async16(uint32_t sa, size_t ga) {
    asm volatile("cp.async.cg.shared.global [%0], [%1], 16;" :: "r"(sa), "l"(ga) : "memory");
}
static __device__ __forceinline__ void cp_commit() {
    asm volatile("cp.async.commit_group;" ::: "memory");
}
template <int N>
static __device__ __forceinline__ void cp_wait() {
    asm volatile("cp.async.wait_group %0;" :: "n"(N) : "memory");
}
static __device__ __forceinline__ void ldsm_x4(uint32_t& r0, uint32_t& r1, uint32_t& r2,
                                               uint32_t& r3, uint32_t addr) {
    asm volatile("ldmatrix.sync.aligned.m8n8.x4.shared.b16 {%0,%1,%2,%3}, [%4];"
                 : "=r"(r0), "=r"(r1), "=r"(r2), "=r"(r3) : "r"(addr));
}
// int8 MMA: D(s32) = A(s8,row) x B(s8,col) + C(s32)
static __device__ __forceinline__ void mma_s8(int* c, uint32_t a0, uint32_t a1,
                                              uint32_t a2, uint32_t a3,
                                              uint32_t b0, uint32_t b1) {
    asm volatile(
        "mma.sync.aligned.m16n8k32.row.col.s32.s8.s8.s32 "
        "{%0,%1,%2,%3}, {%4,%5,%6,%7}, {%8,%9}, {%0,%1,%2,%3};"
        : "+r"(c[0]), "+r"(c[1]), "+r"(c[2]), "+r"(c[3])
        : "r"(a0), "r"(a1), "r"(a2), "r"(a3), "r"(b0), "r"(b1));
}
static __device__ __forceinline__ uint32_t pack4(float a, float b, float c, float d, float inv) {
    int qa = __float2int_rn(a * inv), qb = __float2int_rn(b * inv);
    int qc = __float2int_rn(c * inv), qd = __float2int_rn(d * inv);
    return (uint32_t)(qa & 255) | ((uint32_t)(qb & 255) << 8) |
           ((uint32_t)(qc & 255) << 16) | ((uint32_t)(qd & 255) << 24);
}

// ---------------- kernel 1 (fused prep): x->int8 + rowsum  |  Wq->int8 transposed ----
__global__ void __launch_bounds__(256) prep_kernel(const float* __restrict__ x,
                                                   const int* __restrict__ Wq) {
    // Single 16B-aligned shared frame for both branches (round-7 lesson:
    // unaligned tile base => misaligned ld.shared.v4 trap).
    __shared__ __align__(16) int8_t tile[32][144];
    float* rsum = reinterpret_cast<float*>(&tile[0][0]);
    float* rmax = reinterpret_cast<float*>(&tile[0][64]);
    float* bc   = reinterpret_cast<float*>(&tile[1][0]);

    if (blockIdx.x < TOKENS) {
        const int t = blockIdx.x;
        const int tid = threadIdx.x;
        const float4* xr = reinterpret_cast<const float4*>(x + (size_t)t * KDIM);
        float4 v[4];
        float s = 0.f, mx = 0.f;
#pragma unroll
        for (int j = 0; j < 4; ++j) {
            v[j] = xr[tid * 4 + j];
            s += (v[j].x + v[j].y) + (v[j].z + v[j].w);
            mx = fmaxf(mx, fmaxf(fmaxf(fabsf(v[j].x), fabsf(v[j].y)),
                                 fmaxf(fabsf(v[j].z), fabsf(v[j].w))));
        }
#pragma unroll
        for (int off = 16; off; off >>= 1) {
            s += __shfl_xor_sync(0xFFFFFFFFu, s, off);
            mx = fmaxf(mx, __shfl_xor_sync(0xFFFFFFFFu, mx, off));
        }
        if ((tid & 31) == 0) { rsum[tid >> 5] = s; rmax[tid >> 5] = mx; }
        __syncthreads();
        if (tid == 0) {
            float ts = 0.f, tm = 0.f;
#pragma unroll
            for (int i = 0; i < 8; ++i) { ts += rsum[i]; tm = fmaxf(tm, rmax[i]); }
            g_rowsum[t] = ts;
            g_xscale[t] = tm * (1.f / 127.f);
            bc[0] = (tm > 0.f) ? (127.f / tm) : 0.f;
        }
        __syncthreads();
        const float inv = bc[0];
        uint4 o;
        o.x = pack4(v[0].x, v[0].y, v[0].z, v[0].w, inv);
        o.y = pack4(v[1].x, v[1].y, v[1].z, v[1].w, inv);
        o.z = pack4(v[2].x, v[2].y, v[2].z, v[2].w, inv);
        o.w = pack4(v[3].x, v[3].y, v[3].z, v[3].w, inv);
        *reinterpret_cast<uint4*>(g_xq + (size_t)t * KDIM + tid * 16) = o;
    } else {
        const int idx = blockIdx.x - TOKENS;
        const int n0 = (idx & 127) * 32;
        const int k0 = (idx >> 7) * 128;
        const int tx = threadIdx.x & 31;
        const int ty = threadIdx.x >> 5;
#pragma unroll
        for (int kk = 0; kk < 16; ++kk) {
            const int kr = ty * 16 + kk;
            const int q = Wq[(size_t)(k0 + kr) * NDIM + n0 + tx];
            tile[tx][kr] = (int8_t)(q - 8);
        }
        __syncthreads();
        const int n = threadIdx.x >> 3;
        const int off = (threadIdx.x & 7) * 16;
        uint4 val = *reinterpret_cast<const uint4*>(&tile[n][off]);
        *reinterpret_cast<uint4*>(g_wti + (size_t)(n0 + n) * KDIM + k0 + off) = val;
    }
}

// ---------------- kernel 2: int8 mma GEMM, 2 CTAs/SM, fused epilogue ----------------
__global__ void __launch_bounds__(GEMM_THREADS, 2)
gemm_kernel(const float* __restrict__ scales, const float* __restrict__ u,
            const float* __restrict__ bias, float* __restrict__ out) {
    extern __shared__ char smem[];
    float* u_s  = reinterpret_cast<float*>(smem);
    float* b_s  = reinterpret_cast<float*>(smem + 256);
    float* sc_s = reinterpret_cast<float*>(smem + SC_OFF);   // [32 groups][64 n]
    const uint32_t tiles = smem_u32(smem) + TILE_OFF;

    const int tid = threadIdx.x;
    const int wid = tid >> 5;
    const int lane = tid & 31;
    const int wm = wid & 3;               // 4 x 32 = 128 M
    const int wn = wid >> 2;              // 2 x 32 = 64 N
    const int n0 = blockIdx.x * BN;
    const int m0 = blockIdx.y * BM;

    if (tid < 64) { u_s[tid] = u[n0 + tid]; b_s[tid] = bias[n0 + tid]; }
#pragma unroll
    for (int i = tid; i < NGROUP * 64; i += GEMM_THREADS)
        sc_s[i] = scales[(size_t)(i >> 6) * NDIM + n0 + (i & 63)];

    const size_t ga0 = __cvta_generic_to_global(g_xq) + (size_t)m0 * KDIM;
    const size_t gb0 = __cvta_generic_to_global(g_wti) + (size_t)n0 * KDIM;

    auto issue = [&](int it, int s) {
        const uint32_t a_s = tiles + s * STAGE_BYTES;
        const uint32_t b_sm = a_s + A_STAGE_BYTES;
        const size_t koff = (size_t)it * BK;
        // A: 1024 16B chunks (4/thread); B: 512 chunks (2/thread)
#pragma unroll
        for (int i = 0; i < 4; ++i) {
            int c = tid + i * 256;
            int row = c >> 3, kc = (c & 7) * 16;
            cp_async16(a_s + swz128((uint32_t)(row * 128 + kc)),
                       ga0 + (size_t)row * KDIM + koff + kc);
        }
#pragma unroll
        for (int i = 0; i < 2; ++i) {
            int c = tid + i * 256;
            int row = c >> 3, kc = (c & 7) * 16;
            cp_async16(b_sm + swz128((uint32_t)(row * 128 + kc)),
                       gb0 + (size_t)row * KDIM + koff + kc);
        }
        cp_commit();
    };

#pragma unroll
    for (int s = 0; s < NSTAGE - 1; ++s) issue(s, s);

    float acc_f[2][4][4];
#pragma unroll
    for (int mt = 0; mt < 2; ++mt)
#pragma unroll
        for (int nt = 0; nt < 4; ++nt)
#pragma unroll
            for (int j = 0; j < 4; ++j) acc_f[mt][nt][j] = 0.f;

    const int lrow = lane & 15;
    const int lkb = (lane >> 4) * 16;
    const int cb = wn * 32 + (lane & 3) * 2;   // base output column for this lane

    __syncthreads();   // sc_s / u_s ready

    for (int it = 0; it < KITERS; ++it) {
        cp_wait<NSTAGE - 2>();
        __syncthreads();
        if (it + NSTAGE - 1 < KITERS) issue(it + NSTAGE - 1, (it + NSTAGE - 1) % NSTAGE);

        const int s = it % NSTAGE;
        const uint32_t a_s = tiles + s * STAGE_BYTES;
        const uint32_t b_sm = a_s + A_STAGE_BYTES;

        int acc_i[2][4][4];
#pragma unroll
        for (int mt = 0; mt < 2; ++mt)
#pragma unroll
            for (int nt = 0; nt < 4; ++nt)
#pragma unroll
                for (int j = 0; j < 4; ++j) acc_i[mt][nt][j] = 0;

#pragma unroll
        for (int ks = 0; ks < 4; ++ks) {   // 4 x k32 = one 128-wide group
            const uint32_t kbyte = ks * 32 + lkb;
            uint32_t a[2][4];
#pragma unroll
            for (int mt = 0; mt < 2; ++mt) {
                const int row = wm * 32 + mt * 16 + lrow;
                ldsm_x4(a[mt][0], a[mt][1], a[mt][2], a[mt][3],
                        a_s + swz128((uint32_t)(row * 128) + kbyte));
            }
            uint32_t b[2][4];
#pragma unroll
            for (int p = 0; p < 2; ++p) {
                const int row = wn * 32 + p * 16 + lrow;
                ldsm_x4(b[p][0], b[p][1], b[p][2], b[p][3],
                        b_sm + swz128((uint32_t)(row * 128) + kbyte));
            }
#pragma unroll
            for (int mt = 0; mt < 2; ++mt)
#pragma unroll
                for (int nt = 0; nt < 4; ++nt) {
                    const int p = nt >> 1, h = nt & 1;
                    mma_s8(acc_i[mt][nt], a[mt][0], a[mt][1], a[mt][2], a[mt][3],
                           b[p][h], b[p][2 + h]);
                }
        }
        // per-group dequant into fp32 accumulators
        const float* scg = sc_s + it * 64;
#pragma unroll
        for (int nt = 0; nt < 4; ++nt) {
            const int c0 = cb + nt * 8;
            const float s0 = scg[c0], s1 = scg[c0 + 1];
#pragma unroll
            for (int mt = 0; mt < 2; ++mt) {
                acc_f[mt][nt][0] += s0 * (float)acc_i[mt][nt][0];
                acc_f[mt][nt][1] += s1 * (float)acc_i[mt][nt][1];
                acc_f[mt][nt][2] += s0 * (float)acc_i[mt][nt][2];
                acc_f[mt][nt][3] += s1 * (float)acc_i[mt][nt][3];
            }
        }
    }

    // -------- epilogue: out = sx*acc + rowsum*u + bias --------
#pragma unroll
    for (int mt = 0; mt < 2; ++mt) {
        const int r0 = m0 + wm * 32 + mt * 16 + (lane >> 2);
        const float sx0 = g_xscale[r0], sx1 = g_xscale[r0 + 8];
        const float rs0 = g_rowsum[r0], rs1 = g_rowsum[r0 + 8];
        float* o0 = out + (size_t)r0 * NDIM + n0;
        float* o1 = out + (size_t)(r0 + 8) * NDIM + n0;
#pragma unroll
        for (int nt = 0; nt < 4; ++nt) {
            const int c = cb + nt * 8;
            const float u0 = u_s[c], u1 = u_s[c + 1];
            const float bb0 = b_s[c], bb1 = b_s[c + 1];
            float2 v0, v1;
            v0.x = sx0 * acc_f[mt][nt][0] + rs0 * u0 + bb0;
            v0.y = sx0 * acc_f[mt][nt][1] + rs0 * u1 + bb1;
            v1.x = sx1 * acc_f[mt][nt][2] + rs1 * u0 + bb0;
            v1.y = sx1 * acc_f[mt][nt][3] + rs1 * u1 + bb1;
            *reinterpret_cast<float2*>(o0 + c) = v0;
            *reinterpret_cast<float2*>(o1 + c) = v1;
        }
    }
}

// ---------------- launch ----------------
extern "C" void kernel_launch(void* const* d_in, const int* in_sizes, int n_in,
                              void* d_out, int out_size) {
    const float* x      = (const float*)d_in[0];   // [4*2048*4096]
    const int*   Wq     = (const int*)d_in[1];     // [4096*4096]
    const float* scales = (const float*)d_in[2];   // [32*4096]
    const float* u      = (const float*)d_in[3];   // [4096]
    const float* bias   = (const float*)d_in[4];   // [4096]
    float* out = (float*)d_out;

    cudaFuncSetAttribute(gemm_kernel, cudaFuncAttributeMaxDynamicSharedMemorySize, SMEM_BYTES);

    prep_kernel<<<TOKENS + 4096, 256>>>(x, Wq);
    gemm_kernel<<<dim3(NDIM / BN, TOKENS / BM), GEMM_THREADS, SMEM_BYTES>>>(scales, u, bias, out);
}